// round 16
// baseline (speedup 1.0000x reference)
#include <cuda_runtime.h>
#include <cuda_bf16.h>
#include <math_constants.h>

// Split-kernel filter + exact-rescore attention for cubed-score causal softmax.
//   e = clip(Q·K^T, +-1000)^3 / 8 ; softmax(e) ; O = A·V
// B=2, L=S=2048, H=16, E=D=64, fp32 in/out.
//
// attnA (filter): bf16 mma.sync s~, |s~-s| <= EPS(=0.5); ldmatrix.x4 K frags;
//   128-col macro tiles double-buffered; one epilogue per 128 cols with
//   sthr = cbrt(clip(m_lo)^3-160); warp-vote skip. Candidates -> gmem clist.
//   No Qs smem (A-frags from gmem), no phase-B regs -> 37KB smem, 64 regs, occ 4.
// attnB (rescore): one warp per output row; 8-lane-group exact fp32 K-dots,
//   online softmax, coalesced V gather. Overflow rows -> exact full-prefix pass.
//   (Qrow stride padded to 68 floats = 272B so per-warp float4 loads stay
//    16B-aligned — the 66-float stride caused the round-15 misaligned address.)

#define BQ   64
#define CAP  64
#define NTH  256
#define EPS  0.5f

#define Bb 2
#define Ls 2048
#define Ss 2048
#define Hh 16
#define Ee 64

__device__ __nv_bfloat16  g_Kbf [(size_t)Bb * Ss * Hh * Ee];        // 8 MB
__device__ unsigned short g_clist[(size_t)Bb * Hh * Ls * CAP];      // 8 MB
__device__ unsigned       g_cnt [(size_t)Bb * Hh * Ls];
__device__ unsigned       g_mlo [(size_t)Bb * Hh * Ls];

__device__ __forceinline__ unsigned encf(float f) {
    unsigned u = __float_as_uint(f);
    return u ^ (((unsigned)((int)u >> 31)) | 0x80000000u);
}
__device__ __forceinline__ float decf(unsigned k) {
    unsigned u = (k & 0x80000000u) ? (k ^ 0x80000000u) : ~k;
    return __uint_as_float(u);
}
__device__ __forceinline__ float cube3(float x) {
    x = fminf(fmaxf(x, -1000.f), 1000.f);
    return x * x * x * 0.125f;
}
__device__ __forceinline__ void cp16(void* dst, const void* src) {
    unsigned d = (unsigned)__cvta_generic_to_shared(dst);
    asm volatile("cp.async.cg.shared.global [%0], [%1], 16;" :: "r"(d), "l"(src));
}
#define CP_COMMIT() asm volatile("cp.async.commit_group;")
#define CP_WAIT0()  asm volatile("cp.async.wait_group 0;")

__device__ __forceinline__ void ldm_x4(unsigned& d0, unsigned& d1,
                                       unsigned& d2, unsigned& d3, unsigned addr) {
    asm volatile("ldmatrix.sync.aligned.m8n8.x4.shared.b16 {%0,%1,%2,%3}, [%4];"
                 : "=r"(d0), "=r"(d1), "=r"(d2), "=r"(d3) : "r"(addr));
}
#define MMA16816(c0,c1,c2,c3,a0,a1,a2,a3,b0,b1) \
    asm volatile( \
        "mma.sync.aligned.m16n8k16.row.col.f32.bf16.bf16.f32 " \
        "{%0,%1,%2,%3}, {%4,%5,%6,%7}, {%8,%9}, {%0,%1,%2,%3};" \
        : "+f"(c0), "+f"(c1), "+f"(c2), "+f"(c3) \
        : "r"(a0), "r"(a1), "r"(a2), "r"(a3), "r"(b0), "r"(b1))

// ---- prepass: K fp32 -> bf16 scratch ----
__global__ void cvtK(const float* __restrict__ K) {
    size_t i = ((size_t)blockIdx.x * blockDim.x + threadIdx.x) * 4;
    float4 v = *reinterpret_cast<const float4*>(K + i);
    __nv_bfloat162 lo = __floats2bfloat162_rn(v.x, v.y);
    __nv_bfloat162 hi = __floats2bfloat162_rn(v.z, v.w);
    uint2 o;
    o.x = *reinterpret_cast<unsigned*>(&lo);
    o.y = *reinterpret_cast<unsigned*>(&hi);
    *reinterpret_cast<uint2*>(&g_Kbf[i]) = o;
}

// ============================ Phase A kernel ============================
__global__ void __launch_bounds__(NTH, 4) attnA(
    const float* __restrict__ Qg)
{
    __shared__ __nv_bfloat16 Kb[2][128][72];     // 36864 B
    __shared__ unsigned s_cnt[BQ];
    __shared__ unsigned s_mlo[BQ];

    const int qt  = (int)(gridDim.x - 1) - (int)blockIdx.x;   // longest first
    const int h   = blockIdx.y;
    const int b   = blockIdx.z;
    const int tid = threadIdx.x;
    const int q0  = qt * BQ;
    const size_t rs = (size_t)Hh * Ee;   // 1024

    if (tid < BQ) { s_cnt[tid] = 0u; s_mlo[tid] = 0x007FFFFFu; }  // enc(-inf)

    const int nkt = qt + 1;
    const int nmt = (nkt + 1) >> 1;
    const __nv_bfloat16* Kbase = g_Kbf + (size_t)b * Ss * rs + (size_t)h * Ee;

    // prologue stage of macro tile 0
    {
        int nrows = min(128, nkt * 64);
        #pragma unroll
        for (int it = 0; it < 4; it++) {
            int lin = it * NTH + tid;
            int r = lin >> 3, kc = (lin & 7) * 8;
            if (r < nrows)
                cp16(&Kb[0][r][kc], Kbase + (size_t)r * rs + kc);
        }
        CP_COMMIT();
    }

    // ---- A fragments straight from gmem (once per CTA) ----
    const int w = tid >> 5, lane = tid & 31;
    const int g = lane >> 2, t4 = lane & 3;
    const int rows16 = (w >> 1) * 16;
    const int nhalf  = (w & 1) * 32;
    unsigned afr[4][4];
    {
        const float* Qb = Qg + ((size_t)b * Ls + q0) * rs + (size_t)h * Ee;
        const float* qr0 = Qb + (size_t)(rows16 + g) * rs;
        const float* qr1 = Qb + (size_t)(rows16 + g + 8) * rs;
        #pragma unroll
        for (int ks = 0; ks < 4; ks++) {
            int k0 = ks * 16 + t4 * 2;
            float2 p0 = *reinterpret_cast<const float2*>(qr0 + k0);
            float2 p1 = *reinterpret_cast<const float2*>(qr1 + k0);
            float2 p2 = *reinterpret_cast<const float2*>(qr0 + k0 + 8);
            float2 p3 = *reinterpret_cast<const float2*>(qr1 + k0 + 8);
            __nv_bfloat162 h0 = __floats2bfloat162_rn(p0.x, p0.y);
            __nv_bfloat162 h1 = __floats2bfloat162_rn(p1.x, p1.y);
            __nv_bfloat162 h2 = __floats2bfloat162_rn(p2.x, p2.y);
            __nv_bfloat162 h3 = __floats2bfloat162_rn(p3.x, p3.y);
            afr[ks][0] = *reinterpret_cast<unsigned*>(&h0);
            afr[ks][1] = *reinterpret_cast<unsigned*>(&h1);
            afr[ks][2] = *reinterpret_cast<unsigned*>(&h2);
            afr[ks][3] = *reinterpret_cast<unsigned*>(&h3);
        }
    }

    const int r0 = rows16 + g, r1 = r0 + 8;
    const int rowg0 = q0 + r0, rowg1 = q0 + r1;
    const size_t cb0 = (((size_t)b * Hh + h) * Ls + rowg0) * CAP;
    const size_t cb1 = (((size_t)b * Hh + h) * Ls + rowg1) * CAP;
    const unsigned lmoff = (unsigned)((nhalf + (lane & 7)) * 144 + (lane >> 3) * 16);

    for (int mt = 0; mt < nmt; mt++) {
        CP_WAIT0();
        __syncthreads();
        if (mt + 1 < nmt) {
            int nrows = min(128, nkt * 64 - (mt + 1) * 128);
            const __nv_bfloat16* src = Kbase + (size_t)(mt + 1) * 128 * rs;
            #pragma unroll
            for (int it = 0; it < 4; it++) {
                int lin = it * NTH + tid;
                int r = lin >> 3, kc = (lin & 7) * 8;
                if (r < nrows)
                    cp16(&Kb[(mt + 1) & 1][r][kc], src + (size_t)r * rs + kc);
            }
            CP_COMMIT();
        }
        const int kt0  = mt * 2;
        const int nsub = (nkt - kt0 >= 2) ? 2 : 1;
        const bool hasdiag = (mt == nmt - 1);

        float sf[2][4][4];
        #pragma unroll
        for (int st = 0; st < 2; st++) {
            if (st >= nsub) break;
            const unsigned ktAddr =
                (unsigned)__cvta_generic_to_shared(&Kb[mt & 1][st * 64][0]) + lmoff;
            #pragma unroll
            for (int j = 0; j < 4; j++) {
                unsigned b00, b01, b10, b11, b20, b21, b30, b31;
                unsigned ja = ktAddr + (unsigned)(j * 8 * 144);
                ldm_x4(b00, b01, b10, b11, ja);
                ldm_x4(b20, b21, b30, b31, ja + 64);
                float c0 = 0.f, c1 = 0.f, c2 = 0.f, c3 = 0.f;
                MMA16816(c0,c1,c2,c3, afr[0][0],afr[0][1],afr[0][2],afr[0][3], b00,b01);
                MMA16816(c0,c1,c2,c3, afr[1][0],afr[1][1],afr[1][2],afr[1][3], b10,b11);
                MMA16816(c0,c1,c2,c3, afr[2][0],afr[2][1],afr[2][2],afr[2][3], b20,b21);
                MMA16816(c0,c1,c2,c3, afr[3][0],afr[3][1],afr[3][2],afr[3][3], b30,b31);
                sf[st][j][0] = c0; sf[st][j][1] = c1;
                sf[st][j][2] = c2; sf[st][j][3] = c3;
            }
        }

        float h0 = -CUDART_INF_F, h1 = -CUDART_INF_F;
        #pragma unroll
        for (int st = 0; st < 2; st++) {
            if (st >= nsub) break;
            const bool diag = hasdiag && (kt0 + st == qt);
            #pragma unroll
            for (int j = 0; j < 4; j++) {
                if (diag) {
                    int cg = (kt0 + st) * 64 + nhalf + j * 8 + t4 * 2;
                    if (cg     > rowg0) sf[st][j][0] = -1e30f;
                    if (cg + 1 > rowg0) sf[st][j][1] = -1e30f;
                    if (cg     > rowg1) sf[st][j][2] = -1e30f;
                    if (cg + 1 > rowg1) sf[st][j][3] = -1e30f;
                }
                h0 = fmaxf(h0, fmaxf(sf[st][j][0], sf[st][j][1]));
                h1 = fmaxf(h1, fmaxf(sf[st][j][2], sf[st][j][3]));
            }
        }
        h0 = fmaxf(h0, __shfl_xor_sync(0xffffffffu, h0, 1));
        h0 = fmaxf(h0, __shfl_xor_sync(0xffffffffu, h0, 2));
        h1 = fmaxf(h1, __shfl_xor_sync(0xffffffffu, h1, 1));
        h1 = fmaxf(h1, __shfl_xor_sync(0xffffffffu, h1, 2));

        float lo0 = h0 - EPS, lo1 = h1 - EPS;
        float sthr0 = 0.f, sthr1 = 0.f;
        if (t4 == 0) {
            float m0 = fmaxf(decf(s_mlo[r0]), lo0);
            float m1 = fmaxf(decf(s_mlo[r1]), lo1);
            float mc0 = fminf(fmaxf(m0, -1000.f), 1000.f);
            float mc1 = fminf(fmaxf(m1, -1000.f), 1000.f);
            sthr0 = cbrtf(mc0 * mc0 * mc0 - 160.f);
            sthr1 = cbrtf(mc1 * mc1 * mc1 - 160.f);
            atomicMax(&s_mlo[r0], encf(lo0));
            atomicMax(&s_mlo[r1], encf(lo1));
        }
        sthr0 = __shfl_sync(0xffffffffu, sthr0, lane & ~3);
        sthr1 = __shfl_sync(0xffffffffu, sthr1, lane & ~3);

        bool pass0 = fmaxf(h0 + EPS, -1000.f) >= sthr0;
        bool pass1 = fmaxf(h1 + EPS, -1000.f) >= sthr1;
        if (__any_sync(0xffffffffu, pass0 | pass1)) {
            #pragma unroll
            for (int st = 0; st < 2; st++) {
                if (st >= nsub) break;
                const bool diag = hasdiag && (kt0 + st == qt);
                #pragma unroll
                for (int j = 0; j < 4; j++) {
                    int cg = (kt0 + st) * 64 + nhalf + j * 8 + t4 * 2;
                    bool va0 = !diag || (cg     <= rowg0);
                    bool vb0 = !diag || (cg + 1 <= rowg0);
                    bool va1 = !diag || (cg     <= rowg1);
                    bool vb1 = !diag || (cg + 1 <= rowg1);
                    if (pass0 && va0 && fmaxf(sf[st][j][0] + EPS, -1000.f) >= sthr0) {
                        unsigned idx = atomicAdd(&s_cnt[r0], 1u);
                        if (idx < CAP) g_clist[cb0 + idx] = (unsigned short)cg;
                    }
                    if (pass0 && vb0 && fmaxf(sf[st][j][1] + EPS, -1000.f) >= sthr0) {
                        unsigned idx = atomicAdd(&s_cnt[r0], 1u);
                        if (idx < CAP) g_clist[cb0 + idx] = (unsigned short)(cg + 1);
                    }
                    if (pass1 && va1 && fmaxf(sf[st][j][2] + EPS, -1000.f) >= sthr1) {
                        unsigned idx = atomicAdd(&s_cnt[r1], 1u);
                        if (idx < CAP) g_clist[cb1 + idx] = (unsigned short)cg;
                    }
                    if (pass1 && vb1 && fmaxf(sf[st][j][3] + EPS, -1000.f) >= sthr1) {
                        unsigned idx = atomicAdd(&s_cnt[r1], 1u);
                        if (idx < CAP) g_clist[cb1 + idx] = (unsigned short)(cg + 1);
                    }
                }
            }
        }
    }

    __syncthreads();
    if (tid < BQ) {
        size_t o = ((size_t)b * Hh + h) * Ls + q0 + tid;
        g_cnt[o] = s_cnt[tid];
        g_mlo[o] = s_mlo[tid];
    }
}

// ============================ Phase B kernel ============================
// One warp per output row. 8-lane groups compute exact fp32 rescoring dots
// (4 candidates in flight); whole warp gathers V (float2/lane, 256B coalesced).
__global__ void __launch_bounds__(NTH) attnB(
    const float* __restrict__ Qg, const float* __restrict__ Kg,
    const float* __restrict__ Vg, float* __restrict__ Og)
{
    __shared__ float Qrow[8][68];    // 272B stride: 16B-aligned float4 rows

    const int w    = threadIdx.x >> 5;
    const int lane = threadIdx.x & 31;
    const int row  = blockIdx.x * 8 + w;
    const int h    = blockIdx.y;
    const int b    = blockIdx.z;
    const size_t rs = (size_t)Hh * Ee;   // 1024
    const size_t ro = ((size_t)b * Hh + h) * Ls + row;

    // stage this warp's Q row into smem
    const float* qp = Qg + ((size_t)b * Ls + row) * rs + (size_t)h * Ee;
    *reinterpret_cast<float2*>(&Qrow[w][lane * 2]) =
        *reinterpret_cast<const float2*>(qp + lane * 2);
    __syncwarp();

    unsigned cntv = g_cnt[ro];
    bool ovf = cntv > CAP;
    int nc = ovf ? (row + 1) : (int)cntv;
    float m = ovf ? -CUDART_INF_F : cube3(decf(g_mlo[ro]));
    const unsigned short* cl = g_clist + ro * CAP;

    const int qg = lane >> 3;        // group 0..3 (8 lanes each)
    const int ql = lane & 7;         // position within group

    float acc0 = 0.f, acc1 = 0.f, l = 0.f;

    for (int i0 = 0; i0 < nc; i0 += 4) {
        int ci = i0 + qg;
        bool valid = (ci < nc);
        int col = valid ? (ovf ? ci : (int)cl[ci]) : 0;

        // exact fp32 dot: 8 lanes x 8 elems, butterfly reduce within group
        const float* kp = Kg + ((size_t)b * Ss + col) * rs + (size_t)h * Ee + ql * 8;
        float4 ka = *reinterpret_cast<const float4*>(kp);
        float4 kb = *reinterpret_cast<const float4*>(kp + 4);
        const float* qs = &Qrow[w][ql * 8];
        float4 qa = *reinterpret_cast<const float4*>(qs);
        float4 qb = *reinterpret_cast<const float4*>(qs + 4);
        float s = qa.x * ka.x;
        s = fmaf(qa.y, ka.y, s); s = fmaf(qa.z, ka.z, s); s = fmaf(qa.w, ka.w, s);
        s = fmaf(qb.x, kb.x, s); s = fmaf(qb.y, kb.y, s);
        s = fmaf(qb.z, kb.z, s); s = fmaf(qb.w, kb.w, s);
        s += __shfl_xor_sync(0xffffffffu, s, 1);
        s += __shfl_xor_sync(0xffffffffu, s, 2);
        s += __shfl_xor_sync(0xffffffffu, s, 4);
        float e = valid ? cube3(s) : -1e30f;

        #pragma unroll
        for (int j = 0; j < 4; j++) {
            float ej = __shfl_sync(0xffffffffu, e,   j * 8);
            int   cj = __shfl_sync(0xffffffffu, col, j * 8);
            if (ej > m - 25.f) {                     // warp-uniform branch
                float p;
                if (ej <= m) {
                    p = __expf(ej - m);
                    l += p;
                } else {
                    float al = __expf(m - ej);       // m=-inf -> al=0 (first col)
                    p = 1.f;
                    l = l * al + 1.f;
                    acc0 *= al; acc1 *= al;
                    m = ej;
                }
                const float* vp = Vg + ((size_t)b * Ss + cj) * rs + (size_t)h * Ee + lane * 2;
                float2 v = *reinterpret_cast<const float2*>(vp);
                acc0 = fmaf(p, v.x, acc0);
                acc1 = fmaf(p, v.y, acc1);
            }
        }
    }

    float inv = 1.f / l;
    float* op = Og + ((size_t)b * Ls + row) * rs + (size_t)h * Ee + lane * 2;
    float2 o;
    o.x = acc0 * inv;
    o.y = acc1 * inv;
    *reinterpret_cast<float2*>(op) = o;
}

extern "C" void kernel_launch(void* const* d_in, const int* in_sizes, int n_in,
                              void* d_out, int out_size)
{
    const float* Q = (const float*)d_in[0];
    const float* K = (const float*)d_in[1];
    const float* V = (const float*)d_in[2];
    float* O = (float*)d_out;

    cvtK<<<4096, 256>>>(K);

    dim3 gridA(Ls / BQ, Hh, Bb);
    attnA<<<gridA, NTH>>>(Q);

    dim3 gridB(Ls / 8, Hh, Bb);
    attnB<<<gridB, NTH>>>(Q, K, V, O);
}

// round 17
// speedup vs baseline: 1.0445x; 1.0445x over previous
#include <cuda_runtime.h>
#include <cuda_bf16.h>
#include <math_constants.h>

// Filter + exact-rescore attention for cubed-score causal softmax.
//   e = clip(Q·K^T, +-1000)^3 / 8 ; softmax(e) ; O = A·V
// B=2, L=S=2048, H=16, E=D=64, fp32 in/out.
//
// Phase A: s~ = Q·K^T in bf16 mma.sync (fp32 accum), |s~-s| <= EPS (=0.5).
//   K fragments via ldmatrix.x4; 128-col macro tiles double-buffered (cp.async).
//   One filter epilogue per 128 cols: row max + score-space threshold
//   sthr = cbrt(clip(m_lo)^3 - 160) (m_lo = certified lower bound of row max),
//   warp-vote skip, candidate append. Superset property exact.
// Phase B: exact fp32 online-softmax over candidates (~15-30/row), seeded with
//   the certified phase-A max lower bound; V gather. Overflow -> exact fallback.
// (== round-8 measured-best fused configuration; cvtK widened to 16 elem/thread.)

#define BQ   64
#define CAP  64
#define NTH  256
#define EPS  0.5f

#define Bb 2
#define Ls 2048
#define Ss 2048
#define Hh 16
#define Ee 64

__device__ __nv_bfloat16 g_Kbf[(size_t)Bb * Ss * Hh * Ee];   // 8 MB scratch (static)

struct SmemT {
    float          Qs[BQ][68];          // fp32 Q tile (padded)            17408 B
    __nv_bfloat16  Kb[2][128][72];      // double-buffered 128-col K tile  36864 B
    unsigned short clist[BQ][CAP];      // candidate column ids             8192 B
    unsigned       cnt[BQ];
    unsigned       mlo[BQ];             // order-encoded score-space row-max lower bound
};

__device__ __forceinline__ unsigned encf(float f) {
    unsigned u = __float_as_uint(f);
    return u ^ (((unsigned)((int)u >> 31)) | 0x80000000u);
}
__device__ __forceinline__ float decf(unsigned k) {
    unsigned u = (k & 0x80000000u) ? (k ^ 0x80000000u) : ~k;
    return __uint_as_float(u);
}
__device__ __forceinline__ float cube3(float x) {
    x = fminf(fmaxf(x, -1000.f), 1000.f);
    return x * x * x * 0.125f;
}
__device__ __forceinline__ void cp16(void* dst, const void* src) {
    unsigned d = (unsigned)__cvta_generic_to_shared(dst);
    asm volatile("cp.async.cg.shared.global [%0], [%1], 16;" :: "r"(d), "l"(src));
}
#define CP_COMMIT() asm volatile("cp.async.commit_group;")
#define CP_WAIT0()  asm volatile("cp.async.wait_group 0;")

__device__ __forceinline__ void ldm_x4(unsigned& d0, unsigned& d1,
                                       unsigned& d2, unsigned& d3, unsigned addr) {
    asm volatile("ldmatrix.sync.aligned.m8n8.x4.shared.b16 {%0,%1,%2,%3}, [%4];"
                 : "=r"(d0), "=r"(d1), "=r"(d2), "=r"(d3) : "r"(addr));
}
#define MMA16816(c0,c1,c2,c3,a0,a1,a2,a3,b0,b1) \
    asm volatile( \
        "mma.sync.aligned.m16n8k16.row.col.f32.bf16.bf16.f32 " \
        "{%0,%1,%2,%3}, {%4,%5,%6,%7}, {%8,%9}, {%0,%1,%2,%3};" \
        : "+f"(c0), "+f"(c1), "+f"(c2), "+f"(c3) \
        : "r"(a0), "r"(a1), "r"(a2), "r"(a3), "r"(b0), "r"(b1))

// ---- prepass: K fp32 -> bf16 scratch (16 elems/thread: 2x LDG.128 + STG.128) ----
__global__ void cvtK(const float* __restrict__ K) {
    size_t i = ((size_t)blockIdx.x * blockDim.x + threadIdx.x) * 16;
    float4 v0 = *reinterpret_cast<const float4*>(K + i);
    float4 v1 = *reinterpret_cast<const float4*>(K + i + 4);
    float4 v2 = *reinterpret_cast<const float4*>(K + i + 8);
    float4 v3 = *reinterpret_cast<const float4*>(K + i + 12);
    __nv_bfloat162 h0 = __floats2bfloat162_rn(v0.x, v0.y);
    __nv_bfloat162 h1 = __floats2bfloat162_rn(v0.z, v0.w);
    __nv_bfloat162 h2 = __floats2bfloat162_rn(v1.x, v1.y);
    __nv_bfloat162 h3 = __floats2bfloat162_rn(v1.z, v1.w);
    __nv_bfloat162 h4 = __floats2bfloat162_rn(v2.x, v2.y);
    __nv_bfloat162 h5 = __floats2bfloat162_rn(v2.z, v2.w);
    __nv_bfloat162 h6 = __floats2bfloat162_rn(v3.x, v3.y);
    __nv_bfloat162 h7 = __floats2bfloat162_rn(v3.z, v3.w);
    uint4 oa, ob;
    oa.x = *reinterpret_cast<unsigned*>(&h0);
    oa.y = *reinterpret_cast<unsigned*>(&h1);
    oa.z = *reinterpret_cast<unsigned*>(&h2);
    oa.w = *reinterpret_cast<unsigned*>(&h3);
    ob.x = *reinterpret_cast<unsigned*>(&h4);
    ob.y = *reinterpret_cast<unsigned*>(&h5);
    ob.z = *reinterpret_cast<unsigned*>(&h6);
    ob.w = *reinterpret_cast<unsigned*>(&h7);
    *reinterpret_cast<uint4*>(&g_Kbf[i])     = oa;
    *reinterpret_cast<uint4*>(&g_Kbf[i + 8]) = ob;
}

// stage up to 128 K rows (bf16) into buffer buf; nrows guards tail macro tiles
__device__ __forceinline__ void stageK2(SmemT& sm, int buf,
                                        const __nv_bfloat16* __restrict__ Ksrc,
                                        int tid, int nrows) {
    #pragma unroll
    for (int it = 0; it < 4; it++) {
        int lin = it * NTH + tid;            // 1024 x 16B
        int r = lin >> 3, kc = (lin & 7) * 8;
        if (r < nrows)
            cp16(&sm.Kb[buf][r][kc], Ksrc + (size_t)r * ((size_t)Hh * Ee) + kc);
    }
}

__global__ void __launch_bounds__(NTH, 3) attn(
    const float* __restrict__ Qg, const float* __restrict__ Kg,
    const float* __restrict__ Vg, float* __restrict__ Og)
{
    extern __shared__ char raw[];
    SmemT& sm = *reinterpret_cast<SmemT*>(raw);

    const int qt  = (int)(gridDim.x - 1) - (int)blockIdx.x;   // longest first
    const int h   = blockIdx.y;
    const int b   = blockIdx.z;
    const int tid = threadIdx.x;
    const int q0  = qt * BQ;
    const size_t rs = (size_t)Hh * Ee;   // 1024

    if (tid < BQ) { sm.cnt[tid] = 0u; sm.mlo[tid] = 0x007FFFFFu; }  // enc(-inf)

    // ---- load Q tile fp32 ----
    {
        const float* Qb = Qg + ((size_t)b * Ls + q0) * rs + (size_t)h * Ee;
        #pragma unroll
        for (int it = 0; it < 4; it++) {
            int lin = it * NTH + tid;
            int r = lin >> 4, k4 = (lin & 15) * 4;
            float4 v = *reinterpret_cast<const float4*>(Qb + (size_t)r * rs + k4);
            *reinterpret_cast<float4*>(&sm.Qs[r][k4]) = v;
        }
    }
    const int nkt = qt + 1;               // number of 64-col tiles
    const int nmt = (nkt + 1) >> 1;       // number of 128-col macro tiles
    const __nv_bfloat16* Kbase = g_Kbf + (size_t)b * Ss * rs + (size_t)h * Ee;
    stageK2(sm, 0, Kbase, tid, min(128, nkt * 64));
    CP_COMMIT();
    __syncthreads();

    // ---- A fragments (bf16), registers for whole kernel ----
    const int w = tid >> 5, lane = tid & 31;
    const int g = lane >> 2, t4 = lane & 3;
    const int rows16 = (w >> 1) * 16;
    const int nhalf  = (w & 1) * 32;
    unsigned afr[4][4];
    #pragma unroll
    for (int ks = 0; ks < 4; ks++) {
        int k0 = ks * 16 + t4 * 2;
        float2 p0 = *reinterpret_cast<const float2*>(&sm.Qs[rows16 + g    ][k0    ]);
        float2 p1 = *reinterpret_cast<const float2*>(&sm.Qs[rows16 + g + 8][k0    ]);
        float2 p2 = *reinterpret_cast<const float2*>(&sm.Qs[rows16 + g    ][k0 + 8]);
        float2 p3 = *reinterpret_cast<const float2*>(&sm.Qs[rows16 + g + 8][k0 + 8]);
        __nv_bfloat162 h0 = __floats2bfloat162_rn(p0.x, p0.y);
        __nv_bfloat162 h1 = __floats2bfloat162_rn(p1.x, p1.y);
        __nv_bfloat162 h2 = __floats2bfloat162_rn(p2.x, p2.y);
        __nv_bfloat162 h3 = __floats2bfloat162_rn(p3.x, p3.y);
        afr[ks][0] = *reinterpret_cast<unsigned*>(&h0);
        afr[ks][1] = *reinterpret_cast<unsigned*>(&h1);
        afr[ks][2] = *reinterpret_cast<unsigned*>(&h2);
        afr[ks][3] = *reinterpret_cast<unsigned*>(&h3);
    }

    const int r0 = rows16 + g, r1 = r0 + 8;
    const int rowg0 = q0 + r0, rowg1 = q0 + r1;
    // per-lane ldmatrix row/koffset base (bytes) within a 64-row subtile
    const unsigned lmoff = (unsigned)((nhalf + (lane & 7)) * 144 + (lane >> 3) * 16);

    // =================== Phase A: filter (128-col macro tiles, 1 epilogue) ======
    for (int mt = 0; mt < nmt; mt++) {
        CP_WAIT0();
        __syncthreads();
        if (mt + 1 < nmt) {
            stageK2(sm, (mt + 1) & 1, Kbase + (size_t)(mt + 1) * 128 * rs, tid,
                    min(128, nkt * 64 - (mt + 1) * 128));
            CP_COMMIT();
        }
        const int kt0  = mt * 2;
        const int nsub = (nkt - kt0 >= 2) ? 2 : 1;
        const bool hasdiag = (mt == nmt - 1);        // diag tile == qt == nkt-1

        // ---- MMAs for both subtiles ----
        float sf[2][4][4];
        #pragma unroll
        for (int st = 0; st < 2; st++) {
            if (st >= nsub) break;
            const unsigned ktAddr =
                (unsigned)__cvta_generic_to_shared(&sm.Kb[mt & 1][st * 64][0]) + lmoff;
            #pragma unroll
            for (int j = 0; j < 4; j++) {
                unsigned b00, b01, b10, b11, b20, b21, b30, b31;
                unsigned ja = ktAddr + (unsigned)(j * 8 * 144);
                ldm_x4(b00, b01, b10, b11, ja);        // k 0..31
                ldm_x4(b20, b21, b30, b31, ja + 64);   // k 32..63
                float c0 = 0.f, c1 = 0.f, c2 = 0.f, c3 = 0.f;
                MMA16816(c0,c1,c2,c3, afr[0][0],afr[0][1],afr[0][2],afr[0][3], b00,b01);
                MMA16816(c0,c1,c2,c3, afr[1][0],afr[1][1],afr[1][2],afr[1][3], b10,b11);
                MMA16816(c0,c1,c2,c3, afr[2][0],afr[2][1],afr[2][2],afr[2][3], b20,b21);
                MMA16816(c0,c1,c2,c3, afr[3][0],afr[3][1],afr[3][2],afr[3][3], b30,b31);
                sf[st][j][0] = c0; sf[st][j][1] = c1;
                sf[st][j][2] = c2; sf[st][j][3] = c3;
            }
        }

        // ---- single epilogue over up to 128 columns ----
        float h0 = -CUDART_INF_F, h1 = -CUDART_INF_F;
        #pragma unroll
        for (int st = 0; st < 2; st++) {
            if (st >= nsub) break;
            const bool diag = hasdiag && (kt0 + st == qt);
            #pragma unroll
            for (int j = 0; j < 4; j++) {
                if (diag) {
                    int cg = (kt0 + st) * 64 + nhalf + j * 8 + t4 * 2;
                    if (cg     > rowg0) sf[st][j][0] = -1e30f;
                    if (cg + 1 > rowg0) sf[st][j][1] = -1e30f;
                    if (cg     > rowg1) sf[st][j][2] = -1e30f;
                    if (cg + 1 > rowg1) sf[st][j][3] = -1e30f;
                }
                h0 = fmaxf(h0, fmaxf(sf[st][j][0], sf[st][j][1]));
                h1 = fmaxf(h1, fmaxf(sf[st][j][2], sf[st][j][3]));
            }
        }
        h0 = fmaxf(h0, __shfl_xor_sync(0xffffffffu, h0, 1));
        h0 = fmaxf(h0, __shfl_xor_sync(0xffffffffu, h0, 2));
        h1 = fmaxf(h1, __shfl_xor_sync(0xffffffffu, h1, 1));
        h1 = fmaxf(h1, __shfl_xor_sync(0xffffffffu, h1, 2));

        // score-space threshold, computed once per quad (t4==0), broadcast
        float lo0 = h0 - EPS, lo1 = h1 - EPS;
        float sthr0 = 0.f, sthr1 = 0.f;
        if (t4 == 0) {
            float m0 = fmaxf(decf(sm.mlo[r0]), lo0);
            float m1 = fmaxf(decf(sm.mlo[r1]), lo1);
            float mc0 = fminf(fmaxf(m0, -1000.f), 1000.f);
            float mc1 = fminf(fmaxf(m1, -1000.f), 1000.f);
            sthr0 = cbrtf(mc0 * mc0 * mc0 - 160.f);
            sthr1 = cbrtf(mc1 * mc1 * mc1 - 160.f);
            atomicMax(&sm.mlo[r0], encf(lo0));
            atomicMax(&sm.mlo[r1], encf(lo1));
        }
        sthr0 = __shfl_sync(0xffffffffu, sthr0, lane & ~3);
        sthr1 = __shfl_sync(0xffffffffu, sthr1, lane & ~3);

        // candidate detection, warp-vote early skip (row max implies all elems)
        bool pass0 = fmaxf(h0 + EPS, -1000.f) >= sthr0;
        bool pass1 = fmaxf(h1 + EPS, -1000.f) >= sthr1;
        if (__any_sync(0xffffffffu, pass0 | pass1)) {
            #pragma unroll
            for (int st = 0; st < 2; st++) {
                if (st >= nsub) break;
                const bool diag = hasdiag && (kt0 + st == qt);
                #pragma unroll
                for (int j = 0; j < 4; j++) {
                    int cg = (kt0 + st) * 64 + nhalf + j * 8 + t4 * 2;
                    bool va0 = !diag || (cg     <= rowg0);
                    bool vb0 = !diag || (cg + 1 <= rowg0);
                    bool va1 = !diag || (cg     <= rowg1);
                    bool vb1 = !diag || (cg + 1 <= rowg1);
                    if (pass0 && va0 && fmaxf(sf[st][j][0] + EPS, -1000.f) >= sthr0) {
                        unsigned idx = atomicAdd(&sm.cnt[r0], 1u);
                        if (idx < CAP) sm.clist[r0][idx] = (unsigned short)cg;
                    }
                    if (pass0 && vb0 && fmaxf(sf[st][j][1] + EPS, -1000.f) >= sthr0) {
                        unsigned idx = atomicAdd(&sm.cnt[r0], 1u);
                        if (idx < CAP) sm.clist[r0][idx] = (unsigned short)(cg + 1);
                    }
                    if (pass1 && va1 && fmaxf(sf[st][j][2] + EPS, -1000.f) >= sthr1) {
                        unsigned idx = atomicAdd(&sm.cnt[r1], 1u);
                        if (idx < CAP) sm.clist[r1][idx] = (unsigned short)cg;
                    }
                    if (pass1 && vb1 && fmaxf(sf[st][j][3] + EPS, -1000.f) >= sthr1) {
                        unsigned idx = atomicAdd(&sm.cnt[r1], 1u);
                        if (idx < CAP) sm.clist[r1][idx] = (unsigned short)(cg + 1);
                    }
                }
            }
        }
    }

    __syncthreads();

    // =================== Phase B: exact online rescore ===================
    const int r  = tid >> 2;          // row within tile
    const int qd = tid & 3;           // quad lane: owns d-chunk qd*16
    const int rowg = q0 + r;
    const unsigned qmask = 0xFu << (lane & ~3);
    const int qbase = lane & ~3;

    int cntr = (int)sm.cnt[r];
    bool ovf = cntr > CAP;
    int nc = ovf ? 0 : cntr;

    float4 a0 = {0,0,0,0}, a1 = {0,0,0,0}, a2 = {0,0,0,0}, a3 = {0,0,0,0};
    float l = 0.f;
    // seed m with certified lower bound of true row-max exponent (phase A)
    float m = cube3(decf(sm.mlo[r]));

    if (!ovf) {
        for (int i0 = 0; i0 < nc; i0 += 4) {
            int myi = i0 + qd;
            float e = -1e30f;
            int col = 0;
            if (myi < nc) {
                col = sm.clist[r][myi];
                const float* kp = Kg + ((size_t)b * Ss + col) * rs + (size_t)h * Ee;
                float s = 0.f;
                #pragma unroll
                for (int kk = 0; kk < 16; kk++) {
                    float4 qv = *reinterpret_cast<const float4*>(&sm.Qs[r][kk * 4]);
                    float4 kv = *reinterpret_cast<const float4*>(kp + kk * 4);
                    s = fmaf(qv.x, kv.x, s); s = fmaf(qv.y, kv.y, s);
                    s = fmaf(qv.z, kv.z, s); s = fmaf(qv.w, kv.w, s);
                }
                e = cube3(s);
            }
            #pragma unroll
            for (int jj = 0; jj < 4; jj++) {
                float ej = __shfl_sync(qmask, e,   qbase + jj);
                int   cj = __shfl_sync(qmask, col, qbase + jj);
                if (ej > m - 25.f) {                       // else negligible (< e^-25)
                    float p;
                    if (ej <= m) {                          // common path: no rescale
                        p = __expf(ej - m);
                        l += p;
                    } else {                                // new max: rescale
                        float al = __expf(m - ej);
                        p = 1.f;
                        l = l * al + 1.f;
                        a0.x *= al; a0.y *= al; a0.z *= al; a0.w *= al;
                        a1.x *= al; a1.y *= al; a1.z *= al; a1.w *= al;
                        a2.x *= al; a2.y *= al; a2.z *= al; a2.w *= al;
                        a3.x *= al; a3.y *= al; a3.z *= al; a3.w *= al;
                        m = ej;
                    }
                    const float* vp = Vg + ((size_t)b * Ss + cj) * rs + (size_t)h * Ee + qd * 16;
                    float4 v0 = *reinterpret_cast<const float4*>(vp);
                    float4 v1 = *reinterpret_cast<const float4*>(vp + 4);
                    float4 v2 = *reinterpret_cast<const float4*>(vp + 8);
                    float4 v3 = *reinterpret_cast<const float4*>(vp + 12);
                    a0.x = fmaf(p, v0.x, a0.x); a0.y = fmaf(p, v0.y, a0.y);
                    a0.z = fmaf(p, v0.z, a0.z); a0.w = fmaf(p, v0.w, a0.w);
                    a1.x = fmaf(p, v1.x, a1.x); a1.y = fmaf(p, v1.y, a1.y);
                    a1.z = fmaf(p, v1.z, a1.z); a1.w = fmaf(p, v1.w, a1.w);
                    a2.x = fmaf(p, v2.x, a2.x); a2.y = fmaf(p, v2.y, a2.y);
                    a2.z = fmaf(p, v2.z, a2.z); a2.w = fmaf(p, v2.w, a2.w);
                    a3.x = fmaf(p, v3.x, a3.x); a3.y = fmaf(p, v3.y, a3.y);
                    a3.z = fmaf(p, v3.z, a3.z); a3.w = fmaf(p, v3.w, a3.w);
                }
            }
        }
    } else {
        // exact full-row fallback (capacity overflow; statistically ~never)
        m = -CUDART_INF_F; l = 0.f;
        for (int col = 0; col <= rowg; col++) {
            const float* kp = Kg + ((size_t)b * Ss + col) * rs + (size_t)h * Ee + qd * 16;
            float s = 0.f;
            #pragma unroll
            for (int kk = 0; kk < 4; kk++) {
                float4 qv = *reinterpret_cast<const float4*>(&sm.Qs[r][qd * 16 + kk * 4]);
                float4 kv = *reinterpret_cast<const float4*>(kp + kk * 4);
                s = fmaf(qv.x, kv.x, s); s = fmaf(qv.y, kv.y, s);
                s = fmaf(qv.z, kv.z, s); s = fmaf(qv.w, kv.w, s);
            }
            s += __shfl_xor_sync(qmask, s, 1);
            s += __shfl_xor_sync(qmask, s, 2);
            float e  = cube3(s);
            float mn = fmaxf(m, e);
            float al = __expf(m - mn);
            float p  = __expf(e - mn);
            l = l * al + p;
            const float* vp = Vg + ((size_t)b * Ss + col) * rs + (size_t)h * Ee + qd * 16;
            float4 v0 = *reinterpret_cast<const float4*>(vp);
            float4 v1 = *reinterpret_cast<const float4*>(vp + 4);
            float4 v2 = *reinterpret_cast<const float4*>(vp + 8);
            float4 v3 = *reinterpret_cast<const float4*>(vp + 12);
            a0.x = a0.x * al + p * v0.x; a0.y = a0.y * al + p * v0.y;
            a0.z = a0.z * al + p * v0.z; a0.w = a0.w * al + p * v0.w;
            a1.x = a1.x * al + p * v1.x; a1.y = a1.y * al + p * v1.y;
            a1.z = a1.z * al + p * v1.z; a1.w = a1.w * al + p * v1.w;
            a2.x = a2.x * al + p * v2.x; a2.y = a2.y * al + p * v2.y;
            a2.z = a2.z * al + p * v2.z; a2.w = a2.w * al + p * v2.w;
            a3.x = a3.x * al + p * v3.x; a3.y = a3.y * al + p * v3.y;
            a3.z = a3.z * al + p * v3.z; a3.w = a3.w * al + p * v3.w;
            m = mn;
        }
    }

    float inv = 1.f / l;
    float* op = Og + ((size_t)b * Ls + rowg) * rs + (size_t)h * Ee + qd * 16;
    a0.x *= inv; a0.y *= inv; a0.z *= inv; a0.w *= inv;
    a1.x *= inv; a1.y *= inv; a1.z *= inv; a1.w *= inv;
    a2.x *= inv; a2.y *= inv; a2.z *= inv; a2.w *= inv;
    a3.x *= inv; a3.y *= inv; a3.z *= inv; a3.w *= inv;
    *reinterpret_cast<float4*>(op)      = a0;
    *reinterpret_cast<float4*>(op + 4)  = a1;
    *reinterpret_cast<float4*>(op + 8)  = a2;
    *reinterpret_cast<float4*>(op + 12) = a3;
}

extern "C" void kernel_launch(void* const* d_in, const int* in_sizes, int n_in,
                              void* d_out, int out_size)
{
    const float* Q = (const float*)d_in[0];
    const float* K = (const float*)d_in[1];
    const float* V = (const float*)d_in[2];
    float* O = (float*)d_out;

    cudaFuncSetAttribute(attn, cudaFuncAttributeMaxDynamicSharedMemorySize,
                         (int)sizeof(SmemT));

    cvtK<<<1024, 256>>>(K);   // 16 elems/thread

    dim3 grid(Ls / BQ, Hh, Bb);
    attn<<<grid, NTH, sizeof(SmemT)>>>(Q, K, V, O);
}